// round 11
// baseline (speedup 1.0000x reference)
#include <cuda_runtime.h>
#include <cuda_fp16.h>
#include <float.h>
#include <math.h>
#include <cstdint>

#define BB 8
#define NN 2048
#define DD 512

// ---------------------------------------------------------------------------
// Scratch (__device__ globals only — allocation-free contract)
// ---------------------------------------------------------------------------
__device__ float g_xx[BB * NN];
__device__ __half g_sp[2][(size_t)BB * NN * DD];            // h / l fp16 splits
__device__ uint32_t g_cv[(size_t)BB * NN * 256];            // candidate val bits
__device__ uint32_t g_ci[(size_t)BB * NN * 256];            // candidate global col

__device__ __forceinline__ uint32_t smem_u32(const void* p) {
    uint32_t a;
    asm("{ .reg .u64 t; cvta.to.shared.u64 t, %1; cvt.u32.u64 %0, t; }" : "=r"(a) : "l"(p));
    return a;
}

#define LDSM4(r0, r1, r2, r3, addr) \
    asm volatile("ldmatrix.sync.aligned.m8n8.x4.shared.b16 {%0,%1,%2,%3}, [%4];" \
                 : "=r"(r0), "=r"(r1), "=r"(r2), "=r"(r3) : "r"(addr))

#define MMA16816(c, a, b0, b1) \
    asm volatile("mma.sync.aligned.m16n8k16.row.col.f32.f16.f16.f32 " \
                 "{%0,%1,%2,%3}, {%4,%5,%6,%7}, {%8,%9}, {%0,%1,%2,%3};" \
                 : "+f"((c)[0]), "+f"((c)[1]), "+f"((c)[2]), "+f"((c)[3]) \
                 : "r"((a)[0]), "r"((a)[1]), "r"((a)[2]), "r"((a)[3]), "r"(b0), "r"(b1))

#define CP_ASYNC16(dst, src) \
    asm volatile("cp.async.cg.shared.global [%0], [%1], 16;" :: "r"(dst), "l"(src))
#define CP_COMMIT() asm volatile("cp.async.commit_group;" ::: "memory")

// ---------------------------------------------------------------------------
// Kernel 0: fp16 2-word split of put
// ---------------------------------------------------------------------------
__global__ __launch_bounds__(256) void split_kernel(const float* __restrict__ put) {
    size_t i4 = ((size_t)blockIdx.x * 256 + threadIdx.x) * 4;
    float4 v = *(const float4*)(put + i4);
    float x[4] = {v.x, v.y, v.z, v.w};
    __half h[4], l[4];
#pragma unroll
    for (int q = 0; q < 4; q++) {
        h[q] = __float2half(x[q]);
        l[q] = __float2half(x[q] - __half2float(h[q]));
    }
    *(uint2*)(&g_sp[0][i4]) = *(uint2*)h;
    *(uint2*)(&g_sp[1][i4]) = *(uint2*)l;
}

// ---------------------------------------------------------------------------
// Kernel 1: row squared norms (fp32 exact)
// ---------------------------------------------------------------------------
__global__ __launch_bounds__(256) void xx_kernel(const float* __restrict__ put) {
    int row  = blockIdx.x * 8 + (threadIdx.x >> 5);
    int lane = threadIdx.x & 31;
    const float* p = put + (size_t)row * DD;
    float s = 0.f;
#pragma unroll
    for (int f = 0; f < 4; f++) {
        float4 v = *(const float4*)(p + f * 128 + lane * 4);
        s = fmaf(v.x, v.x, s); s = fmaf(v.y, v.y, s);
        s = fmaf(v.z, v.z, s); s = fmaf(v.w, v.w, s);
    }
#pragma unroll
    for (int off = 16; off; off >>= 1) s += __shfl_xor_sync(0xffffffffu, s, off);
    if (lane == 0) g_xx[row] = s;
}

// ---------------------------------------------------------------------------
// Kernel 2: distance tiles + fused per-tile top-16 selection.
// Writes ONLY 16 (val, col) candidates per row per tile — no dist matrix.
// ---------------------------------------------------------------------------
#define PITCH_H 40
#define TILE_B  (128 * PITCH_H * 2)
#define BUF_B   (4 * TILE_B)
#define XX_OFF  (2 * BUF_B)
#define SM_TOTAL (XX_OFF + 1024)
#define TS_PITCH 129

__global__ __launch_bounds__(256, 1) void dist_mma_kernel() {
    int bx = blockIdx.x, by = blockIdx.y, b = blockIdx.z;
    if (by > bx) return;
    bool diag = (bx == by);
    const uint32_t FULL = 0xffffffffu;

    extern __shared__ char smem[];
    uint32_t sbase = smem_u32(smem);
    int tid  = threadIdx.x;
    int lane = tid & 31;
    int wid  = tid >> 5;

    int j0 = by * 128, i0 = bx * 128, bofs = b * NN;

    float* xxA = (float*)(smem + XX_OFF);
    float* xxB = (float*)(smem + XX_OFF + 512);
    if (tid < 128) {
        xxA[tid] = g_xx[bofs + j0 + tid];
        xxB[tid] = g_xx[bofs + i0 + tid];
    }

    int fr   = (tid >> 2);
    int fck  = tid & 3;
    auto fill = [&](int buf, int kt) {
#pragma unroll
        for (int q = 0; q < 8; q++) {
            int rr   = fr + 64 * (q & 1);
            int tile = q >> 1;
            int word = tile & 1;
            int grow = (tile < 2 ? j0 : i0) + rr;
            const __half* src = &g_sp[word][(size_t)(bofs + grow) * DD + kt * 32 + fck * 8];
            uint32_t dst = sbase + buf * BUF_B + tile * TILE_B + rr * (PITCH_H * 2) + fck * 16;
            CP_ASYNC16(dst, src);
        }
    };

    int wm = (wid >> 2) * 64;
    int wn = (wid & 3) * 32;

    float acc[4][4][4];
#pragma unroll
    for (int im = 0; im < 4; im++)
#pragma unroll
        for (int in = 0; in < 4; in++)
#pragma unroll
            for (int q = 0; q < 4; q++) acc[im][in][q] = 0.f;

    fill(0, 0);
    CP_COMMIT();

    int arow = lane & 15;
    int acol = (lane >> 4) * 8;
    int brow = (lane & 7) + ((lane >> 4) << 3);
    int bcol = ((lane >> 3) & 1) * 8;

    for (int kt = 0; kt < 16; kt++) {
        if (kt < 15) { fill((kt + 1) & 1, kt + 1); CP_COMMIT(); }
        if (kt < 15) asm volatile("cp.async.wait_group 1;" ::: "memory");
        else         asm volatile("cp.async.wait_group 0;" ::: "memory");
        __syncthreads();

        uint32_t base = sbase + (kt & 1) * BUF_B;
#pragma unroll
        for (int kc = 0; kc < 2; kc++) {
            int kofs = kc * 16;
            uint32_t ah[4][4], al[4][4];
#pragma unroll
            for (int im = 0; im < 4; im++) {
                uint32_t off = (uint32_t)((wm + im * 16 + arow) * (PITCH_H * 2) + (kofs + acol) * 2);
                LDSM4(ah[im][0], ah[im][1], ah[im][2], ah[im][3], base + 0 * TILE_B + off);
                LDSM4(al[im][0], al[im][1], al[im][2], al[im][3], base + 1 * TILE_B + off);
            }
            uint32_t bh[8], bl[8];
#pragma unroll
            for (int bp = 0; bp < 2; bp++) {
                uint32_t off = (uint32_t)((wn + bp * 16 + brow) * (PITCH_H * 2) + (kofs + bcol) * 2);
                LDSM4(bh[bp*4+0], bh[bp*4+1], bh[bp*4+2], bh[bp*4+3], base + 2 * TILE_B + off);
                LDSM4(bl[bp*4+0], bl[bp*4+1], bl[bp*4+2], bl[bp*4+3], base + 3 * TILE_B + off);
            }
#pragma unroll
            for (int im = 0; im < 4; im++)
#pragma unroll
                for (int in = 0; in < 4; in++) {
                    MMA16816(acc[im][in], ah[im], bh[in*2], bh[in*2+1]);
                    MMA16816(acc[im][in], ah[im], bl[in*2], bl[in*2+1]);
                    MMA16816(acc[im][in], al[im], bh[in*2], bh[in*2+1]);
                }
        }
        __syncthreads();
    }

    // ---- stage distance tile to smem [128][129] ----
    float* tileS = (float*)smem;
#pragma unroll
    for (int im = 0; im < 4; im++) {
#pragma unroll
        for (int h2 = 0; h2 < 2; h2++) {
            int row = wm + im * 16 + (lane >> 2) + h2 * 8;
            float xj = xxA[row];
#pragma unroll
            for (int in = 0; in < 4; in++) {
                int n = wn + in * 8 + (lane & 3) * 2;
                float g0 = acc[im][in][h2 * 2 + 0];
                float g1 = acc[im][in][h2 * 2 + 1];
                tileS[row * TS_PITCH + n]     = sqrtf(fmaxf((xj + xxB[n])     - 2.0f * g0, 0.0f));
                tileS[row * TS_PITCH + n + 1] = sqrtf(fmaxf((xj + xxB[n + 1]) - 2.0f * g1, 0.0f));
            }
        }
    }
    __syncthreads();

    // ---- per-tile stable top-16: task 0 = rows, task 1 = cols (mirror) ----
    int ntask = diag ? 1 : 2;
    for (int task = 0; task < ntask; task++) {
#pragma unroll 1
        for (int rr = 0; rr < 16; rr++) {
            int loc = wid * 16 + rr;       // local row (task0) / local col (task1)
            unsigned long long pk[4];
#pragma unroll
            for (int k = 0; k < 4; k++) {
                int e = lane + 32 * k;
                float f = (task == 0) ? tileS[loc * TS_PITCH + e]
                                      : tileS[e * TS_PITCH + loc];
                pk[k] = (((unsigned long long)__float_as_uint(f)) << 16) | (unsigned)e;
            }
            uint32_t keepv = 0; int keepi = 0;
#pragma unroll 1
            for (int r = 0; r < 16; r++) {
                unsigned long long best = pk[0];
                if (pk[1] < best) best = pk[1];
                if (pk[2] < best) best = pk[2];
                if (pk[3] < best) best = pk[3];
#pragma unroll
                for (int o = 16; o; o >>= 1) {
                    unsigned long long ob = __shfl_xor_sync(FULL, best, o);
                    if (ob < best) best = ob;
                }
                int col = (int)(best & 0xffffu);
                if (lane == (col & 31)) {
#pragma unroll
                    for (int k = 0; k < 4; k++)
                        if (k == (col >> 5)) pk[k] = ~0ULL;
                }
                if (lane == r) { keepv = (uint32_t)(best >> 16); keepi = col; }
            }
            if (lane < 16) {
                int growSel  = (task == 0) ? (bofs + j0 + loc) : (bofs + i0 + loc);
                int tileIdx  = (task == 0) ? bx : by;
                int colBase  = (task == 0) ? i0 : j0;
                size_t cbase = (size_t)growSel * 256 + tileIdx * 16;
                g_cv[cbase + lane] = keepv;
                g_ci[cbase + lane] = (uint32_t)(colBase + keepi);
            }
        }
    }
}

// ---------------------------------------------------------------------------
// Kernel 3: merge — 1 warp per row, 256 candidates -> top-16, write row.
// Tie-break by slot ≡ tie-break by global col (tiles ordered by col range,
// within-tile rounds emit ascending (val, col)).
// ---------------------------------------------------------------------------
__global__ __launch_bounds__(256) void merge_kernel(float* __restrict__ out) {
    __shared__ uint32_t sci[8][256];
    const uint32_t FULL = 0xffffffffu;
    int tid  = threadIdx.x;
    int lane = tid & 31;
    int wid  = tid >> 5;
    size_t row = (size_t)blockIdx.x * 8 + wid;

    const uint32_t* cvp = g_cv + row * 256;
    const uint32_t* cip = g_ci + row * 256;

    // ci into smem; cv into packed regs
    ((uint4*)sci[wid])[lane * 2]     = ((const uint4*)cip)[lane * 2];
    ((uint4*)sci[wid])[lane * 2 + 1] = ((const uint4*)cip)[lane * 2 + 1];
    uint4 a = ((const uint4*)cvp)[lane * 2];
    uint4 c = ((const uint4*)cvp)[lane * 2 + 1];
    uint32_t v[8] = {a.x, a.y, a.z, a.w, c.x, c.y, c.z, c.w};
    unsigned long long pk[8];
#pragma unroll
    for (int q = 0; q < 8; q++)
        pk[q] = (((unsigned long long)v[q]) << 8) | (unsigned)(lane * 8 + q);
    __syncwarp();

    int mycol = 0;
    bool have = false;
#pragma unroll 1
    for (int r = 0; r < 16; r++) {
        unsigned long long best = pk[0];
#pragma unroll
        for (int q = 1; q < 8; q++) if (pk[q] < best) best = pk[q];
#pragma unroll
        for (int o = 16; o; o >>= 1) {
            unsigned long long ob = __shfl_xor_sync(FULL, best, o);
            if (ob < best) best = ob;
        }
        int s = (int)(best & 0xffu);
        if (lane == (s >> 3)) {
#pragma unroll
            for (int q = 0; q < 8; q++)
                if (q == (s & 7)) pk[q] = ~0ULL;
        }
        if (lane == r) { mycol = (int)sci[wid][s]; have = true; }
    }

    // zero the output row, then scatter 16 ones
    float* orow = out + row * NN;
    float4 z = make_float4(0.f, 0.f, 0.f, 0.f);
#pragma unroll
    for (int k2 = 0; k2 < 16; k2++)
        ((float4*)orow)[lane + 32 * k2] = z;
    __syncwarp();
    if (have) orow[mycol] = 1.0f;
}

// ---------------------------------------------------------------------------
extern "C" void kernel_launch(void* const* d_in, const int* in_sizes, int n_in,
                              void* d_out, int out_size) {
    const float* put = (const float*)d_in[0];
    float* out = (float*)d_out;

    cudaFuncSetAttribute(dist_mma_kernel, cudaFuncAttributeMaxDynamicSharedMemorySize, SM_TOTAL);

    split_kernel<<<(BB * NN * DD) / (256 * 4), 256>>>(put);
    xx_kernel<<<(BB * NN) / 8, 256>>>(put);
    dist_mma_kernel<<<dim3(16, 16, BB), 256, SM_TOTAL>>>();
    merge_kernel<<<(BB * NN) / 8, 256>>>(out);
}

// round 12
// speedup vs baseline: 2.2152x; 2.2152x over previous
#include <cuda_runtime.h>
#include <cuda_fp16.h>
#include <float.h>
#include <math.h>
#include <cstdint>

#define BB 8
#define NN 2048
#define DD 512

// ---------------------------------------------------------------------------
// Scratch (__device__ globals only — allocation-free contract)
// ---------------------------------------------------------------------------
__device__ float g_xx[BB * NN];
__device__ float g_dist[(size_t)BB * NN * NN];              // 134 MB
__device__ __half g_sp[2][(size_t)BB * NN * DD];            // h / l fp16 splits
__device__ unsigned long long g_cand[(size_t)BB * NN * 64]; // 8.4 MB candidates

__device__ __forceinline__ uint32_t smem_u32(const void* p) {
    uint32_t a;
    asm("{ .reg .u64 t; cvta.to.shared.u64 t, %1; cvt.u32.u64 %0, t; }" : "=r"(a) : "l"(p));
    return a;
}

#define LDSM4(r0, r1, r2, r3, addr) \
    asm volatile("ldmatrix.sync.aligned.m8n8.x4.shared.b16 {%0,%1,%2,%3}, [%4];" \
                 : "=r"(r0), "=r"(r1), "=r"(r2), "=r"(r3) : "r"(addr))

#define MMA16816(c, a, b0, b1) \
    asm volatile("mma.sync.aligned.m16n8k16.row.col.f32.f16.f16.f32 " \
                 "{%0,%1,%2,%3}, {%4,%5,%6,%7}, {%8,%9}, {%0,%1,%2,%3};" \
                 : "+f"((c)[0]), "+f"((c)[1]), "+f"((c)[2]), "+f"((c)[3]) \
                 : "r"((a)[0]), "r"((a)[1]), "r"((a)[2]), "r"((a)[3]), "r"(b0), "r"(b1))

#define CP_ASYNC16(dst, src) \
    asm volatile("cp.async.cg.shared.global [%0], [%1], 16;" :: "r"(dst), "l"(src))
#define CP_COMMIT() asm volatile("cp.async.commit_group;" ::: "memory")

// ---------------------------------------------------------------------------
// Kernel 0: fp16 2-word split of put
// ---------------------------------------------------------------------------
__global__ __launch_bounds__(256) void split_kernel(const float* __restrict__ put) {
    size_t i4 = ((size_t)blockIdx.x * 256 + threadIdx.x) * 4;
    float4 v = *(const float4*)(put + i4);
    float x[4] = {v.x, v.y, v.z, v.w};
    __half h[4], l[4];
#pragma unroll
    for (int q = 0; q < 4; q++) {
        h[q] = __float2half(x[q]);
        l[q] = __float2half(x[q] - __half2float(h[q]));
    }
    *(uint2*)(&g_sp[0][i4]) = *(uint2*)h;
    *(uint2*)(&g_sp[1][i4]) = *(uint2*)l;
}

// ---------------------------------------------------------------------------
// Kernel 1: row squared norms (fp32 exact)
// ---------------------------------------------------------------------------
__global__ __launch_bounds__(256) void xx_kernel(const float* __restrict__ put) {
    int row  = blockIdx.x * 8 + (threadIdx.x >> 5);
    int lane = threadIdx.x & 31;
    const float* p = put + (size_t)row * DD;
    float s = 0.f;
#pragma unroll
    for (int f = 0; f < 4; f++) {
        float4 v = *(const float4*)(p + f * 128 + lane * 4);
        s = fmaf(v.x, v.x, s); s = fmaf(v.y, v.y, s);
        s = fmaf(v.z, v.z, s); s = fmaf(v.w, v.w, s);
    }
#pragma unroll
    for (int off = 16; off; off >>= 1) s += __shfl_xor_sync(0xffffffffu, s, off);
    if (lane == 0) g_xx[row] = s;
}

// ---------------------------------------------------------------------------
// Kernel 2: distance tiles (R5-proven form, writes full dist matrix).
// ---------------------------------------------------------------------------
#define PITCH_H 40
#define TILE_B  (128 * PITCH_H * 2)
#define BUF_B   (4 * TILE_B)
#define XX_OFF  (2 * BUF_B)
#define SM_TOTAL (XX_OFF + 1024)
#define T_PITCH 136

__global__ __launch_bounds__(256, 1) void dist_mma_kernel() {
    int bx = blockIdx.x, by = blockIdx.y, b = blockIdx.z;
    if (by > bx) return;
    bool diag = (bx == by);

    extern __shared__ char smem[];
    uint32_t sbase = smem_u32(smem);
    int tid  = threadIdx.x;
    int lane = tid & 31;
    int wid  = tid >> 5;

    int j0 = by * 128, i0 = bx * 128, bofs = b * NN;

    float* xxA = (float*)(smem + XX_OFF);
    float* xxB = (float*)(smem + XX_OFF + 512);
    if (tid < 128) {
        xxA[tid] = g_xx[bofs + j0 + tid];
        xxB[tid] = g_xx[bofs + i0 + tid];
    }

    int fr   = (tid >> 2);
    int fck  = tid & 3;
    auto fill = [&](int buf, int kt) {
#pragma unroll
        for (int q = 0; q < 8; q++) {
            int rr   = fr + 64 * (q & 1);
            int tile = q >> 1;
            int word = tile & 1;
            int grow = (tile < 2 ? j0 : i0) + rr;
            const __half* src = &g_sp[word][(size_t)(bofs + grow) * DD + kt * 32 + fck * 8];
            uint32_t dst = sbase + buf * BUF_B + tile * TILE_B + rr * (PITCH_H * 2) + fck * 16;
            CP_ASYNC16(dst, src);
        }
    };

    int wm = (wid >> 2) * 64;
    int wn = (wid & 3) * 32;

    float acc[4][4][4];
#pragma unroll
    for (int im = 0; im < 4; im++)
#pragma unroll
        for (int in = 0; in < 4; in++)
#pragma unroll
            for (int q = 0; q < 4; q++) acc[im][in][q] = 0.f;

    fill(0, 0);
    CP_COMMIT();

    int arow = lane & 15;
    int acol = (lane >> 4) * 8;
    int brow = (lane & 7) + ((lane >> 4) << 3);
    int bcol = ((lane >> 3) & 1) * 8;

    for (int kt = 0; kt < 16; kt++) {
        if (kt < 15) { fill((kt + 1) & 1, kt + 1); CP_COMMIT(); }
        if (kt < 15) asm volatile("cp.async.wait_group 1;" ::: "memory");
        else         asm volatile("cp.async.wait_group 0;" ::: "memory");
        __syncthreads();

        uint32_t base = sbase + (kt & 1) * BUF_B;
#pragma unroll
        for (int kc = 0; kc < 2; kc++) {
            int kofs = kc * 16;
            uint32_t ah[4][4], al[4][4];
#pragma unroll
            for (int im = 0; im < 4; im++) {
                uint32_t off = (uint32_t)((wm + im * 16 + arow) * (PITCH_H * 2) + (kofs + acol) * 2);
                LDSM4(ah[im][0], ah[im][1], ah[im][2], ah[im][3], base + 0 * TILE_B + off);
                LDSM4(al[im][0], al[im][1], al[im][2], al[im][3], base + 1 * TILE_B + off);
            }
            uint32_t bh[8], bl[8];
#pragma unroll
            for (int bp = 0; bp < 2; bp++) {
                uint32_t off = (uint32_t)((wn + bp * 16 + brow) * (PITCH_H * 2) + (kofs + bcol) * 2);
                LDSM4(bh[bp*4+0], bh[bp*4+1], bh[bp*4+2], bh[bp*4+3], base + 2 * TILE_B + off);
                LDSM4(bl[bp*4+0], bl[bp*4+1], bl[bp*4+2], bl[bp*4+3], base + 3 * TILE_B + off);
            }
#pragma unroll
            for (int im = 0; im < 4; im++)
#pragma unroll
                for (int in = 0; in < 4; in++) {
                    MMA16816(acc[im][in], ah[im], bh[in*2], bh[in*2+1]);
                    MMA16816(acc[im][in], ah[im], bl[in*2], bl[in*2+1]);
                    MMA16816(acc[im][in], al[im], bh[in*2], bh[in*2+1]);
                }
        }
        __syncthreads();
    }

    float* smemT = (float*)smem;

#pragma unroll
    for (int im = 0; im < 4; im++) {
#pragma unroll
        for (int h2 = 0; h2 < 2; h2++) {
            int row = wm + im * 16 + (lane >> 2) + h2 * 8;
            float xj = xxA[row];
#pragma unroll
            for (int in = 0; in < 4; in++) {
                int n = wn + in * 8 + (lane & 3) * 2;
                float g0 = acc[im][in][h2 * 2 + 0];
                float g1 = acc[im][in][h2 * 2 + 1];
                float v0 = sqrtf(fmaxf((xj + xxB[n])     - 2.0f * g0, 0.0f));
                float v1 = sqrtf(fmaxf((xj + xxB[n + 1]) - 2.0f * g1, 0.0f));
                *(float2*)&g_dist[((size_t)(bofs + j0 + row)) * NN + i0 + n] = make_float2(v0, v1);
                if (!diag) {
                    smemT[(n)     * T_PITCH + row] = v0;
                    smemT[(n + 1) * T_PITCH + row] = v1;
                }
            }
        }
    }

    if (!diag) {
        __syncthreads();
#pragma unroll
        for (int q = 0; q < 16; q++) {
            int fid = tid + 256 * q;
            int nrow = fid >> 5, f4 = fid & 31;
            float4 val = *(float4*)&smemT[nrow * T_PITCH + f4 * 4];
            *(float4*)&g_dist[((size_t)(bofs + i0 + nrow)) * NN + j0 + f4 * 4] = val;
        }
    }
}

// ---------------------------------------------------------------------------
// Kernel 3 (stage 1): warp per (row, 512-chunk) — ballot-radix top-16.
// K = (valbits << 16) | idx  (idx = col within chunk; later offset to row col).
// No smem, no block barriers.
// ---------------------------------------------------------------------------
__global__ __launch_bounds__(256) void sel1_kernel() {
    const uint32_t FULL = 0xffffffffu;
    int lane = threadIdx.x & 31;
    int task = blockIdx.x * 8 + (threadIdx.x >> 5);
    int row   = task >> 2;
    int chunk = task & 3;

    const float* src = g_dist + (size_t)row * NN + chunk * 512;
    unsigned long long K[16];
#pragma unroll
    for (int q = 0; q < 4; q++) {
        float4 f = ((const float4*)src)[lane * 4 + q];
        int base = lane * 16 + q * 4;
        K[q*4+0] = (((unsigned long long)__float_as_uint(f.x)) << 16) | (unsigned)(base + 0);
        K[q*4+1] = (((unsigned long long)__float_as_uint(f.y)) << 16) | (unsigned)(base + 1);
        K[q*4+2] = (((unsigned long long)__float_as_uint(f.z)) << 16) | (unsigned)(base + 2);
        K[q*4+3] = (((unsigned long long)__float_as_uint(f.w)) << 16) | (unsigned)(base + 3);
    }

    // 16-step binary descent on value bits [31:16]
    uint32_t P = 0;
#pragma unroll
    for (int b = 15; b >= 0; b--) {
        unsigned long long Tpk = ((unsigned long long)(P | (1u << b))) << 32;
        int c = 0;
#pragma unroll
        for (int q = 0; q < 16; q++) c += (K[q] < Tpk) ? 1 : 0;
        if (__reduce_add_sync(FULL, c) < 16) P |= (1u << b);
    }
    unsigned long long Ppk = ((unsigned long long)P) << 32;
    unsigned long long Qpk = ((unsigned long long)(P + 1ull)) << 32;

    int cl = 0, ce = 0;
#pragma unroll
    for (int q = 0; q < 16; q++) {
        cl += (K[q] < Ppk) ? 1 : 0;
        ce += (K[q] >= Ppk && K[q] < Qpk) ? 1 : 0;
    }
    int clt = __reduce_add_sync(FULL, cl);
    int E   = __reduce_add_sync(FULL, ce);
    int m   = 16 - clt;

    unsigned long long* dst = g_cand + (size_t)row * 64 + chunk * 16;
    unsigned long long addb = (unsigned long long)(chunk * 512);  // idx -> row col

    // sure elements: prefix < P  (count = clt < 16)
    int ps = cl;
#pragma unroll
    for (int o = 1; o < 32; o <<= 1) {
        int t = __shfl_up_sync(FULL, ps, o);
        if (lane >= o) ps += t;
    }
    int slot = ps - cl;
#pragma unroll
    for (int q = 0; q < 16; q++)
        if (K[q] < Ppk) dst[slot++] = K[q] + addb;

    if (E == m) {
        int pe = ce;
#pragma unroll
        for (int o = 1; o < 32; o <<= 1) {
            int t = __shfl_up_sync(FULL, pe, o);
            if (lane >= o) pe += t;
        }
        int slot2 = clt + (pe - ce);
#pragma unroll
        for (int q = 0; q < 16; q++)
            if (K[q] >= Ppk && K[q] < Qpk) dst[slot2++] = K[q] + addb;
    } else {
        // m bounded stable-min rounds over the tied-prefix elements
        for (int it = 0; it < m; it++) {
            unsigned long long best = ~0ull;
#pragma unroll
            for (int q = 0; q < 16; q++)
                if (K[q] >= Ppk && K[q] < Qpk && K[q] < best) best = K[q];
#pragma unroll
            for (int o = 16; o; o >>= 1) {
                unsigned long long ob = __shfl_xor_sync(FULL, best, o);
                if (ob < best) best = ob;
            }
#pragma unroll
            for (int q = 0; q < 16; q++)
                if (K[q] == best) K[q] = ~0ull;     // idx bits make K unique
            if (lane == 0) dst[clt + it] = best + addb;
        }
    }
}

// ---------------------------------------------------------------------------
// Kernel 4 (stage 2): warp per row — merge 64 candidates -> final 16, write.
// K low 16 bits = column within row (0..2047). Exact (val, col) order.
// ---------------------------------------------------------------------------
__global__ __launch_bounds__(256) void sel2_kernel(float* __restrict__ out) {
    const uint32_t FULL = 0xffffffffu;
    int lane = threadIdx.x & 31;
    size_t row = (size_t)blockIdx.x * 8 + (threadIdx.x >> 5);

    const unsigned long long* src = g_cand + row * 64;
    unsigned long long K[2] = { src[lane * 2], src[lane * 2 + 1] };

    // zero the output row while descent happens
    float* orow = out + row * NN;
    float4 z = make_float4(0.f, 0.f, 0.f, 0.f);
#pragma unroll
    for (int q = 0; q < 16; q++)
        ((float4*)orow)[q * 32 + lane] = z;

    uint32_t P = 0;
#pragma unroll
    for (int b = 15; b >= 0; b--) {
        unsigned long long Tpk = ((unsigned long long)(P | (1u << b))) << 32;
        int c = (K[0] < Tpk ? 1 : 0) + (K[1] < Tpk ? 1 : 0);
        if (__reduce_add_sync(FULL, c) < 16) P |= (1u << b);
    }
    unsigned long long Ppk = ((unsigned long long)P) << 32;
    unsigned long long Qpk = ((unsigned long long)(P + 1ull)) << 32;

    int cl = (K[0] < Ppk ? 1 : 0) + (K[1] < Ppk ? 1 : 0);
    int ce = ((K[0] >= Ppk && K[0] < Qpk) ? 1 : 0) + ((K[1] >= Ppk && K[1] < Qpk) ? 1 : 0);
    int clt = __reduce_add_sync(FULL, cl);
    int E   = __reduce_add_sync(FULL, ce);
    int m   = 16 - clt;

    __syncwarp();   // zero-stores ordered before the 1.0 scatters

    // sure
#pragma unroll
    for (int q = 0; q < 2; q++)
        if (K[q] < Ppk) orow[K[q] & 0xffffu] = 1.0f;

    if (E == m) {
#pragma unroll
        for (int q = 0; q < 2; q++)
            if (K[q] >= Ppk && K[q] < Qpk) orow[K[q] & 0xffffu] = 1.0f;
    } else {
        for (int it = 0; it < m; it++) {
            unsigned long long best = ~0ull;
#pragma unroll
            for (int q = 0; q < 2; q++)
                if (K[q] >= Ppk && K[q] < Qpk && K[q] < best) best = K[q];
#pragma unroll
            for (int o = 16; o; o >>= 1) {
                unsigned long long ob = __shfl_xor_sync(FULL, best, o);
                if (ob < best) best = ob;
            }
#pragma unroll
            for (int q = 0; q < 2; q++)
                if (K[q] == best) K[q] = ~0ull;
            if (lane == 0) orow[best & 0xffffu] = 1.0f;
        }
    }
}

// ---------------------------------------------------------------------------
extern "C" void kernel_launch(void* const* d_in, const int* in_sizes, int n_in,
                              void* d_out, int out_size) {
    const float* put = (const float*)d_in[0];
    float* out = (float*)d_out;

    cudaFuncSetAttribute(dist_mma_kernel, cudaFuncAttributeMaxDynamicSharedMemorySize, SM_TOTAL);

    split_kernel<<<(BB * NN * DD) / (256 * 4), 256>>>(put);
    xx_kernel<<<(BB * NN) / 8, 256>>>(put);
    dist_mma_kernel<<<dim3(16, 16, BB), 256, SM_TOTAL>>>();
    sel1_kernel<<<(BB * NN * 4) / 8, 256>>>();
    sel2_kernel<<<(BB * NN) / 8, 256>>>(out);
}

// round 13
// speedup vs baseline: 2.6172x; 1.1815x over previous
#include <cuda_runtime.h>
#include <cuda_fp16.h>
#include <float.h>
#include <math.h>
#include <cstdint>

#define BB 8
#define NN 2048
#define DD 512

// ---------------------------------------------------------------------------
// Scratch (__device__ globals only — allocation-free contract)
// ---------------------------------------------------------------------------
__device__ float g_xx[BB * NN];
__device__ float g_dist[(size_t)BB * NN * NN];              // 134 MB
__device__ __half g_sp[2][(size_t)BB * NN * DD];            // h / l fp16 splits
__device__ unsigned long long g_cand[(size_t)BB * NN * 64]; // 8.4 MB candidates

__device__ __forceinline__ uint32_t smem_u32(const void* p) {
    uint32_t a;
    asm("{ .reg .u64 t; cvta.to.shared.u64 t, %1; cvt.u32.u64 %0, t; }" : "=r"(a) : "l"(p));
    return a;
}

#define LDSM4(r0, r1, r2, r3, addr) \
    asm volatile("ldmatrix.sync.aligned.m8n8.x4.shared.b16 {%0,%1,%2,%3}, [%4];" \
                 : "=r"(r0), "=r"(r1), "=r"(r2), "=r"(r3) : "r"(addr))

#define MMA16816(c, a, b0, b1) \
    asm volatile("mma.sync.aligned.m16n8k16.row.col.f32.f16.f16.f32 " \
                 "{%0,%1,%2,%3}, {%4,%5,%6,%7}, {%8,%9}, {%0,%1,%2,%3};" \
                 : "+f"((c)[0]), "+f"((c)[1]), "+f"((c)[2]), "+f"((c)[3]) \
                 : "r"((a)[0]), "r"((a)[1]), "r"((a)[2]), "r"((a)[3]), "r"(b0), "r"(b1))

#define CP_ASYNC16(dst, src) \
    asm volatile("cp.async.cg.shared.global [%0], [%1], 16;" :: "r"(dst), "l"(src))
#define CP_COMMIT() asm volatile("cp.async.commit_group;" ::: "memory")

// ---------------------------------------------------------------------------
// Kernel 0: fp16 2-word split of put
// ---------------------------------------------------------------------------
__global__ __launch_bounds__(256) void split_kernel(const float* __restrict__ put) {
    size_t i4 = ((size_t)blockIdx.x * 256 + threadIdx.x) * 4;
    float4 v = *(const float4*)(put + i4);
    float x[4] = {v.x, v.y, v.z, v.w};
    __half h[4], l[4];
#pragma unroll
    for (int q = 0; q < 4; q++) {
        h[q] = __float2half(x[q]);
        l[q] = __float2half(x[q] - __half2float(h[q]));
    }
    *(uint2*)(&g_sp[0][i4]) = *(uint2*)h;
    *(uint2*)(&g_sp[1][i4]) = *(uint2*)l;
}

// ---------------------------------------------------------------------------
// Kernel 1: row squared norms (fp32 exact)
// ---------------------------------------------------------------------------
__global__ __launch_bounds__(256) void xx_kernel(const float* __restrict__ put) {
    int row  = blockIdx.x * 8 + (threadIdx.x >> 5);
    int lane = threadIdx.x & 31;
    const float* p = put + (size_t)row * DD;
    float s = 0.f;
#pragma unroll
    for (int f = 0; f < 4; f++) {
        float4 v = *(const float4*)(p + f * 128 + lane * 4);
        s = fmaf(v.x, v.x, s); s = fmaf(v.y, v.y, s);
        s = fmaf(v.z, v.z, s); s = fmaf(v.w, v.w, s);
    }
#pragma unroll
    for (int off = 16; off; off >>= 1) s += __shfl_xor_sync(0xffffffffu, s, off);
    if (lane == 0) g_xx[row] = s;
}

// ---------------------------------------------------------------------------
// Kernel 2: distance tiles (R5-proven form, writes full dist matrix).
// ---------------------------------------------------------------------------
#define PITCH_H 40
#define TILE_B  (128 * PITCH_H * 2)
#define BUF_B   (4 * TILE_B)
#define XX_OFF  (2 * BUF_B)
#define SM_TOTAL (XX_OFF + 1024)
#define T_PITCH 136

__global__ __launch_bounds__(256, 1) void dist_mma_kernel() {
    int bx = blockIdx.x, by = blockIdx.y, b = blockIdx.z;
    if (by > bx) return;
    bool diag = (bx == by);

    extern __shared__ char smem[];
    uint32_t sbase = smem_u32(smem);
    int tid  = threadIdx.x;
    int lane = tid & 31;
    int wid  = tid >> 5;

    int j0 = by * 128, i0 = bx * 128, bofs = b * NN;

    float* xxA = (float*)(smem + XX_OFF);
    float* xxB = (float*)(smem + XX_OFF + 512);
    if (tid < 128) {
        xxA[tid] = g_xx[bofs + j0 + tid];
        xxB[tid] = g_xx[bofs + i0 + tid];
    }

    int fr   = (tid >> 2);
    int fck  = tid & 3;
    auto fill = [&](int buf, int kt) {
#pragma unroll
        for (int q = 0; q < 8; q++) {
            int rr   = fr + 64 * (q & 1);
            int tile = q >> 1;
            int word = tile & 1;
            int grow = (tile < 2 ? j0 : i0) + rr;
            const __half* src = &g_sp[word][(size_t)(bofs + grow) * DD + kt * 32 + fck * 8];
            uint32_t dst = sbase + buf * BUF_B + tile * TILE_B + rr * (PITCH_H * 2) + fck * 16;
            CP_ASYNC16(dst, src);
        }
    };

    int wm = (wid >> 2) * 64;
    int wn = (wid & 3) * 32;

    float acc[4][4][4];
#pragma unroll
    for (int im = 0; im < 4; im++)
#pragma unroll
        for (int in = 0; in < 4; in++)
#pragma unroll
            for (int q = 0; q < 4; q++) acc[im][in][q] = 0.f;

    fill(0, 0);
    CP_COMMIT();

    int arow = lane & 15;
    int acol = (lane >> 4) * 8;
    int brow = (lane & 7) + ((lane >> 4) << 3);
    int bcol = ((lane >> 3) & 1) * 8;

    for (int kt = 0; kt < 16; kt++) {
        if (kt < 15) { fill((kt + 1) & 1, kt + 1); CP_COMMIT(); }
        if (kt < 15) asm volatile("cp.async.wait_group 1;" ::: "memory");
        else         asm volatile("cp.async.wait_group 0;" ::: "memory");
        __syncthreads();

        uint32_t base = sbase + (kt & 1) * BUF_B;
#pragma unroll
        for (int kc = 0; kc < 2; kc++) {
            int kofs = kc * 16;
            uint32_t ah[4][4], al[4][4];
#pragma unroll
            for (int im = 0; im < 4; im++) {
                uint32_t off = (uint32_t)((wm + im * 16 + arow) * (PITCH_H * 2) + (kofs + acol) * 2);
                LDSM4(ah[im][0], ah[im][1], ah[im][2], ah[im][3], base + 0 * TILE_B + off);
                LDSM4(al[im][0], al[im][1], al[im][2], al[im][3], base + 1 * TILE_B + off);
            }
            uint32_t bh[8], bl[8];
#pragma unroll
            for (int bp = 0; bp < 2; bp++) {
                uint32_t off = (uint32_t)((wn + bp * 16 + brow) * (PITCH_H * 2) + (kofs + bcol) * 2);
                LDSM4(bh[bp*4+0], bh[bp*4+1], bh[bp*4+2], bh[bp*4+3], base + 2 * TILE_B + off);
                LDSM4(bl[bp*4+0], bl[bp*4+1], bl[bp*4+2], bl[bp*4+3], base + 3 * TILE_B + off);
            }
#pragma unroll
            for (int im = 0; im < 4; im++)
#pragma unroll
                for (int in = 0; in < 4; in++) {
                    MMA16816(acc[im][in], ah[im], bh[in*2], bh[in*2+1]);
                    MMA16816(acc[im][in], ah[im], bl[in*2], bl[in*2+1]);
                    MMA16816(acc[im][in], al[im], bh[in*2], bh[in*2+1]);
                }
        }
        __syncthreads();
    }

    float* smemT = (float*)smem;

#pragma unroll
    for (int im = 0; im < 4; im++) {
#pragma unroll
        for (int h2 = 0; h2 < 2; h2++) {
            int row = wm + im * 16 + (lane >> 2) + h2 * 8;
            float xj = xxA[row];
#pragma unroll
            for (int in = 0; in < 4; in++) {
                int n = wn + in * 8 + (lane & 3) * 2;
                float g0 = acc[im][in][h2 * 2 + 0];
                float g1 = acc[im][in][h2 * 2 + 1];
                float v0 = sqrtf(fmaxf((xj + xxB[n])     - 2.0f * g0, 0.0f));
                float v1 = sqrtf(fmaxf((xj + xxB[n + 1]) - 2.0f * g1, 0.0f));
                *(float2*)&g_dist[((size_t)(bofs + j0 + row)) * NN + i0 + n] = make_float2(v0, v1);
                if (!diag) {
                    smemT[(n)     * T_PITCH + row] = v0;
                    smemT[(n + 1) * T_PITCH + row] = v1;
                }
            }
        }
    }

    if (!diag) {
        __syncthreads();
#pragma unroll
        for (int q = 0; q < 16; q++) {
            int fid = tid + 256 * q;
            int nrow = fid >> 5, f4 = fid & 31;
            float4 val = *(float4*)&smemT[nrow * T_PITCH + f4 * 4];
            *(float4*)&g_dist[((size_t)(bofs + i0 + nrow)) * NN + j0 + f4 * 4] = val;
        }
    }
}

// ---------------------------------------------------------------------------
// Kernel 3 (stage 1): warp per (row, 512-chunk) — ballot-radix top-16 with
// pure 32-bit descent. Keys stay as raw fp32 bits in 16 u32 regs; the index
// is reconstructed from the register slot (col = chunk*512 + lane*16 + s).
// ---------------------------------------------------------------------------
__global__ __launch_bounds__(256) void sel1_kernel() {
    const uint32_t FULL = 0xffffffffu;
    int lane = threadIdx.x & 31;
    int task = blockIdx.x * 8 + (threadIdx.x >> 5);
    int row   = task >> 2;
    int chunk = task & 3;

    const float* src = g_dist + (size_t)row * NN + chunk * 512;
    uint32_t V[16];
#pragma unroll
    for (int q = 0; q < 4; q++) {
        float4 f = ((const float4*)src)[lane * 4 + q];
        V[q*4+0] = __float_as_uint(f.x);
        V[q*4+1] = __float_as_uint(f.y);
        V[q*4+2] = __float_as_uint(f.z);
        V[q*4+3] = __float_as_uint(f.w);
    }

    // 16-step binary descent on value bits [31:16] — pure u32 compares.
    uint32_t P = 0;
#pragma unroll
    for (int b = 15; b >= 0; b--) {
        uint32_t T = (P | (1u << b)) << 16;      // low 16 bits zero
        int c = 0;
#pragma unroll
        for (int q = 0; q < 16; q++) c += (V[q] < T) ? 1 : 0;
        if (__reduce_add_sync(FULL, c) < 16) P |= (1u << b);
    }
    uint32_t Plo = P << 16;

    int cl = 0, ce = 0;
#pragma unroll
    for (int q = 0; q < 16; q++) {
        cl += (V[q] < Plo) ? 1 : 0;
        ce += ((V[q] >> 16) == P) ? 1 : 0;
    }
    int clt = __reduce_add_sync(FULL, cl);
    int E   = __reduce_add_sync(FULL, ce);
    int m   = 16 - clt;

    unsigned long long* dst = g_cand + (size_t)row * 64 + chunk * 16;
    int colbase = chunk * 512 + lane * 16;

    // sure elements (val top bits < P): prefix-scan slots, write u64 keys
    int ps = cl;
#pragma unroll
    for (int o = 1; o < 32; o <<= 1) {
        int t = __shfl_up_sync(FULL, ps, o);
        if (lane >= o) ps += t;
    }
    int slot = ps - cl;
#pragma unroll
    for (int q = 0; q < 16; q++)
        if (V[q] < Plo)
            dst[slot++] = (((unsigned long long)V[q]) << 16) | (unsigned)(colbase + q);

    if (E == m) {
        int pe = ce;
#pragma unroll
        for (int o = 1; o < 32; o <<= 1) {
            int t = __shfl_up_sync(FULL, pe, o);
            if (lane >= o) pe += t;
        }
        int slot2 = clt + (pe - ce);
#pragma unroll
        for (int q = 0; q < 16; q++)
            if ((V[q] >> 16) == P)
                dst[slot2++] = (((unsigned long long)V[q]) << 16) | (unsigned)(colbase + q);
    } else {
        // m bounded stable-min rounds over tied-prefix elements (u64 order)
        for (int it = 0; it < m; it++) {
            unsigned long long best = ~0ull;
#pragma unroll
            for (int q = 0; q < 16; q++) {
                if ((V[q] >> 16) == P) {
                    unsigned long long K =
                        (((unsigned long long)V[q]) << 16) | (unsigned)(colbase + q);
                    if (K < best) best = K;
                }
            }
#pragma unroll
            for (int o = 16; o; o >>= 1) {
                unsigned long long ob = __shfl_xor_sync(FULL, best, o);
                if (ob < best) best = ob;
            }
            // remove the winner: its slot is unique (col encodes slot)
            int bcol = (int)(best & 0xffffu);
            if ((bcol >> 4) == (colbase >> 4) && (bcol & ~15) == colbase)
                V[bcol & 15] = 0xffffffffu;       // tombstone (top bits ≠ P)
            if (lane == 0) dst[clt + it] = best;
        }
    }
}

// ---------------------------------------------------------------------------
// Kernel 4 (stage 2): warp per row — merge 64 candidates -> final 16, write.
// ---------------------------------------------------------------------------
__global__ __launch_bounds__(256) void sel2_kernel(float* __restrict__ out) {
    const uint32_t FULL = 0xffffffffu;
    int lane = threadIdx.x & 31;
    size_t row = (size_t)blockIdx.x * 8 + (threadIdx.x >> 5);

    const unsigned long long* src = g_cand + row * 64;
    unsigned long long K[2] = { src[lane * 2], src[lane * 2 + 1] };

    float* orow = out + row * NN;
    float4 z = make_float4(0.f, 0.f, 0.f, 0.f);
#pragma unroll
    for (int q = 0; q < 16; q++)
        ((float4*)orow)[q * 32 + lane] = z;

    uint32_t P = 0;
#pragma unroll
    for (int b = 15; b >= 0; b--) {
        unsigned long long Tpk = ((unsigned long long)(P | (1u << b))) << 32;
        int c = (K[0] < Tpk ? 1 : 0) + (K[1] < Tpk ? 1 : 0);
        if (__reduce_add_sync(FULL, c) < 16) P |= (1u << b);
    }
    unsigned long long Ppk = ((unsigned long long)P) << 32;
    unsigned long long Qpk = ((unsigned long long)(P + 1ull)) << 32;

    int cl = (K[0] < Ppk ? 1 : 0) + (K[1] < Ppk ? 1 : 0);
    int ce = ((K[0] >= Ppk && K[0] < Qpk) ? 1 : 0) + ((K[1] >= Ppk && K[1] < Qpk) ? 1 : 0);
    int clt = __reduce_add_sync(FULL, cl);
    int E   = __reduce_add_sync(FULL, ce);
    int m   = 16 - clt;

    __syncwarp();   // zero-stores ordered before the 1.0 scatters

#pragma unroll
    for (int q = 0; q < 2; q++)
        if (K[q] < Ppk) orow[K[q] & 0xffffu] = 1.0f;

    if (E == m) {
#pragma unroll
        for (int q = 0; q < 2; q++)
            if (K[q] >= Ppk && K[q] < Qpk) orow[K[q] & 0xffffu] = 1.0f;
    } else {
        for (int it = 0; it < m; it++) {
            unsigned long long best = ~0ull;
#pragma unroll
            for (int q = 0; q < 2; q++)
                if (K[q] >= Ppk && K[q] < Qpk && K[q] < best) best = K[q];
#pragma unroll
            for (int o = 16; o; o >>= 1) {
                unsigned long long ob = __shfl_xor_sync(FULL, best, o);
                if (ob < best) best = ob;
            }
#pragma unroll
            for (int q = 0; q < 2; q++)
                if (K[q] == best) K[q] = ~0ull;
            if (lane == 0) orow[best & 0xffffu] = 1.0f;
        }
    }
}

// ---------------------------------------------------------------------------
extern "C" void kernel_launch(void* const* d_in, const int* in_sizes, int n_in,
                              void* d_out, int out_size) {
    const float* put = (const float*)d_in[0];
    float* out = (float*)d_out;

    cudaFuncSetAttribute(dist_mma_kernel, cudaFuncAttributeMaxDynamicSharedMemorySize, SM_TOTAL);

    split_kernel<<<(BB * NN * DD) / (256 * 4), 256>>>(put);
    xx_kernel<<<(BB * NN) / 8, 256>>>(put);
    dist_mma_kernel<<<dim3(16, 16, BB), 256, SM_TOTAL>>>();
    sel1_kernel<<<(BB * NN * 4) / 8, 256>>>();
    sel2_kernel<<<(BB * NN) / 8, 256>>>(out);
}

// round 17
// speedup vs baseline: 3.0308x; 1.1581x over previous
#include <cuda_runtime.h>
#include <cuda_fp16.h>
#include <float.h>
#include <math.h>
#include <cstdint>

#define BB 8
#define NN 2048
#define DD 512

// ---------------------------------------------------------------------------
// Scratch (__device__ globals only — allocation-free contract)
// ---------------------------------------------------------------------------
__device__ float g_xx[BB * NN];
__device__ float g_dist[(size_t)BB * NN * NN];              // 134 MB
__device__ __half g_sp[2][(size_t)BB * NN * DD];            // h / l fp16 splits
__device__ unsigned long long g_cand[(size_t)BB * NN * 64]; // 8.4 MB candidates

__device__ __forceinline__ uint32_t smem_u32(const void* p) {
    uint32_t a;
    asm("{ .reg .u64 t; cvta.to.shared.u64 t, %1; cvt.u32.u64 %0, t; }" : "=r"(a) : "l"(p));
    return a;
}

#define LDSM4(r0, r1, r2, r3, addr) \
    asm volatile("ldmatrix.sync.aligned.m8n8.x4.shared.b16 {%0,%1,%2,%3}, [%4];" \
                 : "=r"(r0), "=r"(r1), "=r"(r2), "=r"(r3) : "r"(addr))

#define MMA16816(c, a, b0, b1) \
    asm volatile("mma.sync.aligned.m16n8k16.row.col.f32.f16.f16.f32 " \
                 "{%0,%1,%2,%3}, {%4,%5,%6,%7}, {%8,%9}, {%0,%1,%2,%3};" \
                 : "+f"((c)[0]), "+f"((c)[1]), "+f"((c)[2]), "+f"((c)[3]) \
                 : "r"((a)[0]), "r"((a)[1]), "r"((a)[2]), "r"((a)[3]), "r"(b0), "r"(b1))

#define CP_ASYNC16(dst, src) \
    asm volatile("cp.async.cg.shared.global [%0], [%1], 16;" :: "r"(dst), "l"(src))
#define CP_COMMIT() asm volatile("cp.async.commit_group;" ::: "memory")

// ---------------------------------------------------------------------------
// Kernel 0: fp16 2-word split of put
// ---------------------------------------------------------------------------
__global__ __launch_bounds__(256) void split_kernel(const float* __restrict__ put) {
    size_t i4 = ((size_t)blockIdx.x * 256 + threadIdx.x) * 4;
    float4 v = *(const float4*)(put + i4);
    float x[4] = {v.x, v.y, v.z, v.w};
    __half h[4], l[4];
#pragma unroll
    for (int q = 0; q < 4; q++) {
        h[q] = __float2half(x[q]);
        l[q] = __float2half(x[q] - __half2float(h[q]));
    }
    *(uint2*)(&g_sp[0][i4]) = *(uint2*)h;
    *(uint2*)(&g_sp[1][i4]) = *(uint2*)l;
}

// ---------------------------------------------------------------------------
// Kernel 1: row squared norms (fp32 exact)
// ---------------------------------------------------------------------------
__global__ __launch_bounds__(256) void xx_kernel(const float* __restrict__ put) {
    int row  = blockIdx.x * 8 + (threadIdx.x >> 5);
    int lane = threadIdx.x & 31;
    const float* p = put + (size_t)row * DD;
    float s = 0.f;
#pragma unroll
    for (int f = 0; f < 4; f++) {
        float4 v = *(const float4*)(p + f * 128 + lane * 4);
        s = fmaf(v.x, v.x, s); s = fmaf(v.y, v.y, s);
        s = fmaf(v.z, v.z, s); s = fmaf(v.w, v.w, s);
    }
#pragma unroll
    for (int off = 16; off; off >>= 1) s += __shfl_xor_sync(0xffffffffu, s, off);
    if (lane == 0) g_xx[row] = s;
}

// ---------------------------------------------------------------------------
// Kernel 2: distance tiles (R5-proven form, writes full dist matrix).
// ---------------------------------------------------------------------------
#define PITCH_H 40
#define TILE_B  (128 * PITCH_H * 2)
#define BUF_B   (4 * TILE_B)
#define XX_OFF  (2 * BUF_B)
#define SM_TOTAL (XX_OFF + 1024)
#define T_PITCH 136

__global__ __launch_bounds__(256, 1) void dist_mma_kernel() {
    int bx = blockIdx.x, by = blockIdx.y, b = blockIdx.z;
    if (by > bx) return;
    bool diag = (bx == by);

    extern __shared__ char smem[];
    uint32_t sbase = smem_u32(smem);
    int tid  = threadIdx.x;
    int lane = tid & 31;
    int wid  = tid >> 5;

    int j0 = by * 128, i0 = bx * 128, bofs = b * NN;

    float* xxA = (float*)(smem + XX_OFF);
    float* xxB = (float*)(smem + XX_OFF + 512);
    if (tid < 128) {
        xxA[tid] = g_xx[bofs + j0 + tid];
        xxB[tid] = g_xx[bofs + i0 + tid];
    }

    int fr   = (tid >> 2);
    int fck  = tid & 3;
    auto fill = [&](int buf, int kt) {
#pragma unroll
        for (int q = 0; q < 8; q++) {
            int rr   = fr + 64 * (q & 1);
            int tile = q >> 1;
            int word = tile & 1;
            int grow = (tile < 2 ? j0 : i0) + rr;
            const __half* src = &g_sp[word][(size_t)(bofs + grow) * DD + kt * 32 + fck * 8];
            uint32_t dst = sbase + buf * BUF_B + tile * TILE_B + rr * (PITCH_H * 2) + fck * 16;
            CP_ASYNC16(dst, src);
        }
    };

    int wm = (wid >> 2) * 64;
    int wn = (wid & 3) * 32;

    float acc[4][4][4];
#pragma unroll
    for (int im = 0; im < 4; im++)
#pragma unroll
        for (int in = 0; in < 4; in++)
#pragma unroll
            for (int q = 0; q < 4; q++) acc[im][in][q] = 0.f;

    fill(0, 0);
    CP_COMMIT();

    int arow = lane & 15;
    int acol = (lane >> 4) * 8;
    int brow = (lane & 7) + ((lane >> 4) << 3);
    int bcol = ((lane >> 3) & 1) * 8;

    for (int kt = 0; kt < 16; kt++) {
        if (kt < 15) { fill((kt + 1) & 1, kt + 1); CP_COMMIT(); }
        if (kt < 15) asm volatile("cp.async.wait_group 1;" ::: "memory");
        else         asm volatile("cp.async.wait_group 0;" ::: "memory");
        __syncthreads();

        uint32_t base = sbase + (kt & 1) * BUF_B;
#pragma unroll
        for (int kc = 0; kc < 2; kc++) {
            int kofs = kc * 16;
            uint32_t ah[4][4], al[4][4];
#pragma unroll
            for (int im = 0; im < 4; im++) {
                uint32_t off = (uint32_t)((wm + im * 16 + arow) * (PITCH_H * 2) + (kofs + acol) * 2);
                LDSM4(ah[im][0], ah[im][1], ah[im][2], ah[im][3], base + 0 * TILE_B + off);
                LDSM4(al[im][0], al[im][1], al[im][2], al[im][3], base + 1 * TILE_B + off);
            }
            uint32_t bh[8], bl[8];
#pragma unroll
            for (int bp = 0; bp < 2; bp++) {
                uint32_t off = (uint32_t)((wn + bp * 16 + brow) * (PITCH_H * 2) + (kofs + bcol) * 2);
                LDSM4(bh[bp*4+0], bh[bp*4+1], bh[bp*4+2], bh[bp*4+3], base + 2 * TILE_B + off);
                LDSM4(bl[bp*4+0], bl[bp*4+1], bl[bp*4+2], bl[bp*4+3], base + 3 * TILE_B + off);
            }
#pragma unroll
            for (int im = 0; im < 4; im++)
#pragma unroll
                for (int in = 0; in < 4; in++) {
                    MMA16816(acc[im][in], ah[im], bh[in*2], bh[in*2+1]);
                    MMA16816(acc[im][in], ah[im], bl[in*2], bl[in*2+1]);
                    MMA16816(acc[im][in], al[im], bh[in*2], bh[in*2+1]);
                }
        }
        __syncthreads();
    }

    float* smemT = (float*)smem;

#pragma unroll
    for (int im = 0; im < 4; im++) {
#pragma unroll
        for (int h2 = 0; h2 < 2; h2++) {
            int row = wm + im * 16 + (lane >> 2) + h2 * 8;
            float xj = xxA[row];
#pragma unroll
            for (int in = 0; in < 4; in++) {
                int n = wn + in * 8 + (lane & 3) * 2;
                float g0 = acc[im][in][h2 * 2 + 0];
                float g1 = acc[im][in][h2 * 2 + 1];
                float v0 = sqrtf(fmaxf((xj + xxB[n])     - 2.0f * g0, 0.0f));
                float v1 = sqrtf(fmaxf((xj + xxB[n + 1]) - 2.0f * g1, 0.0f));
                *(float2*)&g_dist[((size_t)(bofs + j0 + row)) * NN + i0 + n] = make_float2(v0, v1);
                if (!diag) {
                    smemT[(n)     * T_PITCH + row] = v0;
                    smemT[(n + 1) * T_PITCH + row] = v1;
                }
            }
        }
    }

    if (!diag) {
        __syncthreads();
#pragma unroll
        for (int q = 0; q < 16; q++) {
            int fid = tid + 256 * q;
            int nrow = fid >> 5, f4 = fid & 31;
            float4 val = *(float4*)&smemT[nrow * T_PITCH + f4 * 4];
            *(float4*)&g_dist[((size_t)(bofs + i0 + nrow)) * NN + j0 + f4 * 4] = val;
        }
    }
}

// ---------------------------------------------------------------------------
// Kernel 3 (stage 1): warp per (row, 512-chunk) — prefiltered ballot-radix.
//  1) thread-min; 2) descent on the 32 minima -> prefix bound P1
//     (16th-smallest element <= 16th-smallest thread-min => its prefix <= P1)
//  3) compact survivors (prefix <= P1, ~30 of 512) into 4 regs/thread
//  4) exact descent on survivors (final P/clt/E provably identical to full)
//  Overflow (>4 survivors on any thread) -> full 16-element descent fallback.
// ---------------------------------------------------------------------------
__global__ __launch_bounds__(256) void sel1_kernel() {
    const uint32_t FULL = 0xffffffffu;
    int lane = threadIdx.x & 31;
    int task = blockIdx.x * 8 + (threadIdx.x >> 5);
    int row   = task >> 2;
    int chunk = task & 3;

    const float* src = g_dist + (size_t)row * NN + chunk * 512;
    uint32_t V[16];
#pragma unroll
    for (int q = 0; q < 4; q++) {
        float4 f = ((const float4*)src)[lane * 4 + q];
        V[q*4+0] = __float_as_uint(f.x);
        V[q*4+1] = __float_as_uint(f.y);
        V[q*4+2] = __float_as_uint(f.z);
        V[q*4+3] = __float_as_uint(f.w);
    }
    int colbase = chunk * 512 + lane * 16;
    unsigned long long* dst = g_cand + (size_t)row * 64 + chunk * 16;

    // 1) thread-local min (positive floats: unsigned bit order == value order)
    uint32_t tmin = V[0];
#pragma unroll
    for (int q = 1; q < 16; q++) tmin = umin(tmin, V[q]);

    // 2) descent over the 32 minima -> P1
    uint32_t P1 = 0;
#pragma unroll
    for (int b = 15; b >= 0; b--) {
        uint32_t T = (P1 | (1u << b)) << 16;
        int c = (tmin < T) ? 1 : 0;
        if (__reduce_add_sync(FULL, c) < 16) P1 |= (1u << b);
    }

    // 3) branch-free compaction of survivors (prefix <= P1), cap 4/thread
    uint32_t A0 = FULL, A1 = FULL, A2 = FULL, A3 = FULL, qs = 0;
    int n = 0;
#pragma unroll
    for (int q = 0; q < 16; q++) {
        if ((V[q] >> 16) <= P1) {
            A3 = A2; A2 = A1; A1 = A0; A0 = V[q];
            qs = (qs << 4) | (uint32_t)q;
            n++;
        }
    }

    if (__reduce_max_sync(FULL, (unsigned)n) <= 4u) {
        // 4) exact descent on survivors
        uint32_t A[4] = {A0, A1, A2, A3};
        uint32_t col[4] = { (uint32_t)colbase + (qs & 15u),
                            (uint32_t)colbase + ((qs >> 4) & 15u),
                            (uint32_t)colbase + ((qs >> 8) & 15u),
                            (uint32_t)colbase + ((qs >> 12) & 15u) };
        uint32_t P = 0;
#pragma unroll
        for (int b = 15; b >= 0; b--) {
            uint32_t T = (P | (1u << b)) << 16;
            int c = (A[0] < T ? 1 : 0) + (A[1] < T ? 1 : 0)
                  + (A[2] < T ? 1 : 0) + (A[3] < T ? 1 : 0);
            if (__reduce_add_sync(FULL, c) < 16) P |= (1u << b);
        }
        uint32_t Plo = P << 16;

        int cl = 0, ce = 0;
#pragma unroll
        for (int q = 0; q < 4; q++) {
            cl += (A[q] < Plo) ? 1 : 0;
            ce += ((A[q] >> 16) == P) ? 1 : 0;
        }
        int clt = __reduce_add_sync(FULL, cl);
        int E   = __reduce_add_sync(FULL, ce);
        int m   = 16 - clt;

        int ps = cl;
#pragma unroll
        for (int o = 1; o < 32; o <<= 1) {
            int t = __shfl_up_sync(FULL, ps, o);
            if (lane >= o) ps += t;
        }
        int slot = ps - cl;
#pragma unroll
        for (int q = 0; q < 4; q++)
            if (A[q] < Plo)
                dst[slot++] = (((unsigned long long)A[q]) << 16) | col[q];

        if (E == m) {
            int pe = ce;
#pragma unroll
            for (int o = 1; o < 32; o <<= 1) {
                int t = __shfl_up_sync(FULL, pe, o);
                if (lane >= o) pe += t;
            }
            int slot2 = clt + (pe - ce);
#pragma unroll
            for (int q = 0; q < 4; q++)
                if ((A[q] >> 16) == P)
                    dst[slot2++] = (((unsigned long long)A[q]) << 16) | col[q];
        } else {
            for (int it = 0; it < m; it++) {
                unsigned long long best = ~0ull;
#pragma unroll
                for (int q = 0; q < 4; q++)
                    if ((A[q] >> 16) == P) {
                        unsigned long long K =
                            (((unsigned long long)A[q]) << 16) | col[q];
                        if (K < best) best = K;
                    }
#pragma unroll
                for (int o = 16; o; o >>= 1) {
                    unsigned long long ob = __shfl_xor_sync(FULL, best, o);
                    if (ob < best) best = ob;
                }
#pragma unroll
                for (int q = 0; q < 4; q++)
                    if ((A[q] >> 16) == P &&
                        ((((unsigned long long)A[q]) << 16) | col[q]) == best)
                        A[q] = FULL;
                if (lane == 0) dst[clt + it] = best;
            }
        }
    } else {
        // -------- overflow fallback: full 16-element descent (R13) --------
        uint32_t P = 0;
#pragma unroll
        for (int b = 15; b >= 0; b--) {
            uint32_t T = (P | (1u << b)) << 16;
            int c = 0;
#pragma unroll
            for (int q = 0; q < 16; q++) c += (V[q] < T) ? 1 : 0;
            if (__reduce_add_sync(FULL, c) < 16) P |= (1u << b);
        }
        uint32_t Plo = P << 16;

        int cl = 0, ce = 0;
#pragma unroll
        for (int q = 0; q < 16; q++) {
            cl += (V[q] < Plo) ? 1 : 0;
            ce += ((V[q] >> 16) == P) ? 1 : 0;
        }
        int clt = __reduce_add_sync(FULL, cl);
        int E   = __reduce_add_sync(FULL, ce);
        int m   = 16 - clt;

        int ps = cl;
#pragma unroll
        for (int o = 1; o < 32; o <<= 1) {
            int t = __shfl_up_sync(FULL, ps, o);
            if (lane >= o) ps += t;
        }
        int slot = ps - cl;
#pragma unroll
        for (int q = 0; q < 16; q++)
            if (V[q] < Plo)
                dst[slot++] = (((unsigned long long)V[q]) << 16) | (unsigned)(colbase + q);

        if (E == m) {
            int pe = ce;
#pragma unroll
            for (int o = 1; o < 32; o <<= 1) {
                int t = __shfl_up_sync(FULL, pe, o);
                if (lane >= o) pe += t;
            }
            int slot2 = clt + (pe - ce);
#pragma unroll
            for (int q = 0; q < 16; q++)
                if ((V[q] >> 16) == P)
                    dst[slot2++] = (((unsigned long long)V[q]) << 16) | (unsigned)(colbase + q);
        } else {
            for (int it = 0; it < m; it++) {
                unsigned long long best = ~0ull;
#pragma unroll
                for (int q = 0; q < 16; q++) {
                    if ((V[q] >> 16) == P) {
                        unsigned long long K =
                            (((unsigned long long)V[q]) << 16) | (unsigned)(colbase + q);
                        if (K < best) best = K;
                    }
                }
#pragma unroll
                for (int o = 16; o; o >>= 1) {
                    unsigned long long ob = __shfl_xor_sync(FULL, best, o);
                    if (ob < best) best = ob;
                }
                int bcol = (int)(best & 0xffffu);
                if ((bcol & ~15) == colbase)
                    V[bcol & 15] = 0xffffffffu;
                if (lane == 0) dst[clt + it] = best;
            }
        }
    }
}

// ---------------------------------------------------------------------------
// Kernel 4 (stage 2): warp per row — merge 64 candidates -> final 16, write.
// ---------------------------------------------------------------------------
__global__ __launch_bounds__(256) void sel2_kernel(float* __restrict__ out) {
    const uint32_t FULL = 0xffffffffu;
    int lane = threadIdx.x & 31;
    size_t row = (size_t)blockIdx.x * 8 + (threadIdx.x >> 5);

    const unsigned long long* src = g_cand + row * 64;
    unsigned long long K[2] = { src[lane * 2], src[lane * 2 + 1] };

    float* orow = out + row * NN;
    float4 z = make_float4(0.f, 0.f, 0.f, 0.f);
#pragma unroll
    for (int q = 0; q < 16; q++)
        ((float4*)orow)[q * 32 + lane] = z;

    uint32_t P = 0;
#pragma unroll
    for (int b = 15; b >= 0; b--) {
        unsigned long long Tpk = ((unsigned long long)(P | (1u << b))) << 32;
        int c = (K[0] < Tpk ? 1 : 0) + (K[1] < Tpk ? 1 : 0);
        if (__reduce_add_sync(FULL, c) < 16) P |= (1u << b);
    }
    unsigned long long Ppk = ((unsigned long long)P) << 32;
    unsigned long long Qpk = ((unsigned long long)(P + 1ull)) << 32;

    int cl = (K[0] < Ppk ? 1 : 0) + (K[1] < Ppk ? 1 : 0);
    int ce = ((K[0] >= Ppk && K[0] < Qpk) ? 1 : 0) + ((K[1] >= Ppk && K[1] < Qpk) ? 1 : 0);
    int clt = __reduce_add_sync(FULL, cl);
    int E   = __reduce_add_sync(FULL, ce);
    int m   = 16 - clt;

    __syncwarp();   // zero-stores ordered before the 1.0 scatters

#pragma unroll
    for (int q = 0; q < 2; q++)
        if (K[q] < Ppk) orow[K[q] & 0xffffu] = 1.0f;

    if (E == m) {
#pragma unroll
        for (int q = 0; q < 2; q++)
            if (K[q] >= Ppk && K[q] < Qpk) orow[K[q] & 0xffffu] = 1.0f;
    } else {
        for (int it = 0; it < m; it++) {
            unsigned long long best = ~0ull;
#pragma unroll
            for (int q = 0; q < 2; q++)
                if (K[q] >= Ppk && K[q] < Qpk && K[q] < best) best = K[q];
#pragma unroll
            for (int o = 16; o; o >>= 1) {
                unsigned long long ob = __shfl_xor_sync(FULL, best, o);
                if (ob < best) best = ob;
            }
#pragma unroll
            for (int q = 0; q < 2; q++)
                if (K[q] == best) K[q] = ~0ull;
            if (lane == 0) orow[best & 0xffffu] = 1.0f;
        }
    }
}

// ---------------------------------------------------------------------------
extern "C" void kernel_launch(void* const* d_in, const int* in_sizes, int n_in,
                              void* d_out, int out_size) {
    const float* put = (const float*)d_in[0];
    float* out = (float*)d_out;

    cudaFuncSetAttribute(dist_mma_kernel, cudaFuncAttributeMaxDynamicSharedMemorySize, SM_TOTAL);

    split_kernel<<<(BB * NN * DD) / (256 * 4), 256>>>(put);
    xx_kernel<<<(BB * NN) / 8, 256>>>(put);
    dist_mma_kernel<<<dim3(16, 16, BB), 256, SM_TOTAL>>>();
    sel1_kernel<<<(BB * NN * 4) / 8, 256>>>();
    sel2_kernel<<<(BB * NN) / 8, 256>>>(out);
}